// round 15
// baseline (speedup 1.0000x reference)
#include <cuda_runtime.h>
#include <cuda_fp16.h>
#include <cstdint>

// PatchAttentionLayer on GB300 (sm_103 baseline PTX path).
// BN folded into affine maps; attention via associativity (no NxN map).
// R13: proj's 42us latency-bound Cov walk replaced by a proper fp32 GEMM
// (WC = W*Cov) + cheap epilogue. Everything else as R12 (170us, 3.0e-4).

#define CCH 256
#define BATCH 8
#define HWN 4096
#define EPS_BN 1e-5f
#define INV_NPOS (1.0f / 32768.0f)
#define SCALE 0.125f

// ================= device scratch =================
__device__ __half g_xh[BATCH][CCH][HWN];   // fp16 x, [c][p]
__device__ float g_S1p[4][BATCH][CCH][CCH];
__device__ float g_s[BATCH][CCH];
__device__ float g_mean[CCH];
__device__ float g_Cov[CCH][CCH];
__device__ float g_WC[3][CCH][CCH];        // W_tp * Cov
__device__ float g_A[3][CCH][CCH];
__device__ float g_cvec[3][CCH];
__device__ float g_G[BATCH][CCH][CCH];
__device__ float g_T1[BATCH][CCH][CCH];
__device__ float g_M[BATCH][CCH][CCH];
__device__ float g_d[BATCH][CCH];
__device__ __half g_Ph[BATCH][CCH][CCH];

// ================= mma helpers (sm_80+ baseline PTX) =================
__device__ __forceinline__ uint32_t smem_u32(const void* p) {
    uint32_t a;
    asm("{ .reg .u64 t; cvta.to.shared.u64 t, %1; cvt.u32.u64 %0, t; }" : "=r"(a) : "l"(p));
    return a;
}
__device__ __forceinline__ void ldsm4(uint32_t* r, uint32_t a) {
    asm volatile("ldmatrix.sync.aligned.m8n8.x4.shared.b16 {%0,%1,%2,%3}, [%4];"
                 : "=r"(r[0]), "=r"(r[1]), "=r"(r[2]), "=r"(r[3]) : "r"(a));
}
__device__ __forceinline__ void ldsm4t(uint32_t* r, uint32_t a) {
    asm volatile("ldmatrix.sync.aligned.m8n8.x4.trans.shared.b16 {%0,%1,%2,%3}, [%4];"
                 : "=r"(r[0]), "=r"(r[1]), "=r"(r[2]), "=r"(r[3]) : "r"(a));
}
__device__ __forceinline__ void mma_f16(float* c, const uint32_t* a, const uint32_t* b) {
    asm volatile(
        "mma.sync.aligned.m16n8k16.row.col.f32.f16.f16.f32 "
        "{%0,%1,%2,%3},{%4,%5,%6,%7},{%8,%9},{%0,%1,%2,%3};"
        : "+f"(c[0]), "+f"(c[1]), "+f"(c[2]), "+f"(c[3])
        : "r"(a[0]), "r"(a[1]), "r"(a[2]), "r"(a[3]), "r"(b[0]), "r"(b[1]));
}
#define CPA16(dst, src) asm volatile("cp.async.cg.shared.global [%0], [%1], 16;" :: "r"(dst), "l"(src))
#define CPA_COMMIT()    asm volatile("cp.async.commit_group;")
#define CPA_WAIT1()     asm volatile("cp.async.wait_group 1;")
#define CPA_WAIT0()     asm volatile("cp.async.wait_group 0;")

// ================= prep: fp32 -> fp16 + per-(b,c) sums =================
__global__ __launch_bounds__(256) void prep_kernel(const float* __restrict__ x) {
    int c = blockIdx.x, b = blockIdx.y;
    const float4* src = (const float4*)(x + ((long)(b * CCH + c)) * HWN);
    __half2* dh = (__half2*)&g_xh[b][c][0];
    float s = 0.f;
    for (int i = threadIdx.x; i < 1024; i += 256) {
        float4 v = src[i];
        s += (v.x + v.y) + (v.z + v.w);
        dh[2 * i]     = __halves2half2(__float2half_rn(v.x), __float2half_rn(v.y));
        dh[2 * i + 1] = __halves2half2(__float2half_rn(v.z), __float2half_rn(v.w));
    }
    __shared__ float sh[256];
    sh[threadIdx.x] = s;
    __syncthreads();
    for (int off = 128; off > 0; off >>= 1) {
        if (threadIdx.x < off) sh[threadIdx.x] += sh[threadIdx.x + off];
        __syncthreads();
    }
    if (threadIdx.x == 0) g_s[b][c] = sh[0];
}

// ================= gram: S1 = H H^T (fp16 mma, split-K x4) =================
#define GR_TILE 10240
#define GR_BUF  (2 * GR_TILE)
#define GR_SMEM (2 * GR_BUF)

__global__ __launch_bounds__(256) void gram_mma_kernel() {
    extern __shared__ char smem[];
    uint32_t sb = smem_u32(smem);
    int t = threadIdx.x, lane = t & 31, wid = t >> 5;
    int split = blockIdx.x, b = blockIdx.z;
    int mt = blockIdx.y >> 1, nt = blockIdx.y & 1;
    const __half* Ag = &g_xh[b][mt * 128][0];
    const __half* Bg = &g_xh[b][nt * 128][0];
    int k0 = split * 1024;
    int wm = (wid >> 2) * 64, wn = (wid & 3) * 32;

    float acc[4][4][4] = {};

    auto stage = [&](int buf, int kk) {
        uint32_t base = sb + buf * GR_BUF;
#pragma unroll
        for (int i = t; i < 512; i += 256) {
            int r = i >> 2, c = i & 3;
            long go = (long)r * HWN + kk + c * 8;
            uint32_t so = r * 80 + c * 16;
            CPA16(base + so,           (const char*)(Ag + go));
            CPA16(base + GR_TILE + so, (const char*)(Bg + go));
        }
    };

    stage(0, k0);
    CPA_COMMIT();
    const int S = 32;
    for (int s = 0; s < S; s++) {
        if (s + 1 < S) { stage((s + 1) & 1, k0 + (s + 1) * 32); CPA_COMMIT(); CPA_WAIT1(); }
        else CPA_WAIT0();
        __syncthreads();
        uint32_t aBase = sb + (s & 1) * GR_BUF;
        uint32_t bBase = aBase + GR_TILE;
#pragma unroll
        for (int ks = 0; ks < 32; ks += 16) {
            uint32_t af[4][4], bf[4][2];
#pragma unroll
            for (int i = 0; i < 4; i++)
                ldsm4(af[i], aBase + (wm + i * 16 + (lane & 15)) * 80 + ks * 2 + (lane >> 4) * 16);
#pragma unroll
            for (int j = 0; j < 2; j++) {
                uint32_t r[4];
                ldsm4(r, bBase + (wn + j * 16 + (lane & 15)) * 80 + ks * 2 + (lane >> 4) * 16);
                bf[2 * j][0] = r[0]; bf[2 * j][1] = r[2];
                bf[2 * j + 1][0] = r[1]; bf[2 * j + 1][1] = r[3];
            }
#pragma unroll
            for (int i = 0; i < 4; i++)
#pragma unroll
                for (int j = 0; j < 4; j++) mma_f16(acc[i][j], af[i], bf[j]);
        }
        __syncthreads();
    }

    float* dst = &g_S1p[split][b][0][0];
#pragma unroll
    for (int i = 0; i < 4; i++) {
        int m = mt * 128 + wm + i * 16 + (lane >> 2);
#pragma unroll
        for (int j = 0; j < 4; j++) {
            int n = nt * 128 + wn + j * 8 + (lane & 3) * 2;
            *(float2*)(dst + (long)m * CCH + n) = make_float2(acc[i][j][0], acc[i][j][1]);
            *(float2*)(dst + (long)(m + 8) * CCH + n) = make_float2(acc[i][j][2], acc[i][j][3]);
        }
    }
}

// ================= reduceG + cov + mean fused =================
__global__ __launch_bounds__(256) void reduceG_cov_kernel() {
    int jt = blockIdx.x * 32, it = blockIdx.y * 32;
    int lx = threadIdx.x & 31, ly = threadIdx.x >> 5;
    float mc = 0.f;
#pragma unroll
    for (int b = 0; b < BATCH; b++) mc += g_s[b][jt + lx];
    mc *= INV_NPOS;
    float gsum[4] = {};
    for (int b = 0; b < BATCH; b++) {
#pragma unroll
        for (int q = 0; q < 4; q++) {
            int r = ly + q * 8;
            float s = 0.f;
#pragma unroll
            for (int sp = 0; sp < 4; sp++) s += g_S1p[sp][b][it + r][jt + lx];
            g_G[b][it + r][jt + lx] = s;
            gsum[q] += s;
        }
    }
#pragma unroll
    for (int q = 0; q < 4; q++) {
        int r = ly + q * 8;
        float mr = 0.f;
#pragma unroll
        for (int b = 0; b < BATCH; b++) mr += g_s[b][it + r];
        mr *= INV_NPOS;
        g_Cov[it + r][jt + lx] = gsum[q] * INV_NPOS - mr * mc;
    }
    if (blockIdx.x == 0 && blockIdx.y == 0) {
        int t = threadIdx.x;
        float m = 0.f;
#pragma unroll
        for (int b = 0; b < BATCH; b++) m += g_s[b][t];
        g_mean[t] = m * INV_NPOS;
    }
}

// ================= fp32 glue GEMM micro-kernel =================
__device__ __forceinline__ void mma16f(const float (*As)[65], const float (*Bs)[65],
                                       int ty, int tx, float acc[4][4]) {
#pragma unroll
    for (int kk = 0; kk < 16; kk++) {
        float a[4], b[4];
#pragma unroll
        for (int i = 0; i < 4; i++) a[i] = As[kk][ty * 4 + i];
#pragma unroll
        for (int j = 0; j < 4; j++) b[j] = Bs[kk][tx * 4 + j];
#pragma unroll
        for (int i = 0; i < 4; i++)
#pragma unroll
            for (int j = 0; j < 4; j++) acc[i][j] += a[i] * b[j];
    }
}

// ================= WC[tp] = W_tp * Cov (NN fp32 GEMM) =================
__global__ void wcov_kernel(const float* __restrict__ Wq,
                            const float* __restrict__ Wk,
                            const float* __restrict__ Wv) {
    int tp = blockIdx.z;
    const float* A = (tp == 0) ? Wq : (tp == 1) ? Wk : Wv;   // [o][c]
    int rowBase = blockIdx.y * 64, colBase = blockIdx.x * 64;
    __shared__ float As[16][65], Bs[16][65];
    int t = threadIdx.x, tx = t & 15, ty = t >> 4;
    int ar = t >> 2, akseg = (t & 3) * 4;
    int bkk = t >> 4, bcc = (t & 15) * 4;
    float acc[4][4] = {};
    const float* B = &g_Cov[0][0];
    for (int k0 = 0; k0 < CCH; k0 += 16) {
        float4 av = *(const float4*)(A + (rowBase + ar) * CCH + k0 + akseg);
        float4 bv = *(const float4*)(B + (k0 + bkk) * CCH + colBase + bcc);
        As[akseg + 0][ar] = av.x; As[akseg + 1][ar] = av.y; As[akseg + 2][ar] = av.z; As[akseg + 3][ar] = av.w;
        Bs[bkk][bcc + 0] = bv.x; Bs[bkk][bcc + 1] = bv.y; Bs[bkk][bcc + 2] = bv.z; Bs[bkk][bcc + 3] = bv.w;
        __syncthreads();
        mma16f(As, Bs, ty, tx, acc);
        __syncthreads();
    }
#pragma unroll
    for (int i = 0; i < 4; i++)
#pragma unroll
        for (int j = 0; j < 4; j++)
            g_WC[tp][rowBase + ty * 4 + i][colBase + tx * 4 + j] = acc[i][j];
}

// ================= projfin: var from WC, fold BN =================
__global__ __launch_bounds__(256) void projfin_kernel(
    const float* __restrict__ Wq, const float* __restrict__ bq, const float* __restrict__ gq, const float* __restrict__ beq,
    const float* __restrict__ Wk, const float* __restrict__ bk, const float* __restrict__ gk, const float* __restrict__ bek,
    const float* __restrict__ Wv, const float* __restrict__ bv, const float* __restrict__ gv, const float* __restrict__ bev) {
    __shared__ float s1[256], s2[256];
    __shared__ float a_sh, c_sh;
    int t = threadIdx.x;
    int base = blockIdx.x * 8;
    int tp = base >> 8, o0 = base & 255;
    const float *W, *bb, *gg, *be;
    if (tp == 0) { W = Wq; bb = bq; gg = gq; be = beq; }
    else if (tp == 1) { W = Wk; bb = bk; gg = gk; be = bek; }
    else { W = Wv; bb = bv; gg = gv; be = bev; }
    float mt_ = g_mean[t];
#pragma unroll
    for (int r = 0; r < 8; r++) {
        int o = o0 + r;
        float w = W[o * CCH + t];
        s1[t] = g_WC[tp][o][t] * w;
        s2[t] = w * mt_;
        __syncthreads();
        for (int off = 128; off > 0; off >>= 1) {
            if (t < off) { s1[t] += s1[t + off]; s2[t] += s2[t + off]; }
            __syncthreads();
        }
        if (t == 0) {
            float var = s1[0];
            float mu = s2[0] + bb[o];
            float a = gg[o] * rsqrtf(var + EPS_BN);
            a_sh = a;
            c_sh = (bb[o] - mu) * a + be[o];
        }
        __syncthreads();
        g_A[tp][o][t] = a_sh * w;
        if (t == 0) g_cvec[tp][o] = c_sh;
        __syncthreads();
    }
}

// T1_b = G_b * Ak^T (NT)
__global__ void t1_kernel() {
    int b = blockIdx.z;
    int rowBase = blockIdx.y * 64, colBase = blockIdx.x * 64;
    __shared__ float As[16][65], Bs[16][65];
    int t = threadIdx.x, tx = t & 15, ty = t >> 4;
    int r = t >> 2, kseg = (t & 3) * 4;
    float acc[4][4] = {};
    const float* A = &g_G[b][0][0];
    const float* B = &g_A[1][0][0];
    for (int k0 = 0; k0 < CCH; k0 += 16) {
        float4 av = *(const float4*)(A + (rowBase + r) * CCH + k0 + kseg);
        float4 bv = *(const float4*)(B + (colBase + r) * CCH + k0 + kseg);
        As[kseg + 0][r] = av.x; As[kseg + 1][r] = av.y; As[kseg + 2][r] = av.z; As[kseg + 3][r] = av.w;
        Bs[kseg + 0][r] = bv.x; Bs[kseg + 1][r] = bv.y; Bs[kseg + 2][r] = bv.z; Bs[kseg + 3][r] = bv.w;
        __syncthreads();
        mma16f(As, Bs, ty, tx, acc);
        __syncthreads();
    }
#pragma unroll
    for (int i = 0; i < 4; i++)
#pragma unroll
        for (int j = 0; j < 4; j++)
            g_T1[b][rowBase + ty * 4 + i][colBase + tx * 4 + j] = acc[i][j];
}

// M_b = Av * T1_b + rank-1 corrections (uw fused in prologue)
__global__ void m_kernel() {
    int b = blockIdx.z;
    int rowBase = blockIdx.y * 64, colBase = blockIdx.x * 64;
    __shared__ float As[16][65], Bs[16][65];
    __shared__ float ss[CCH], su[64], sw[64];
    int t = threadIdx.x, tx = t & 15, ty = t >> 4;
    int ar = t >> 2, akseg = (t & 3) * 4;
    int bkk = t >> 4, bcc = (t & 15) * 4;
    ss[t] = g_s[b][t];
    __syncthreads();
    if (t < 64) {
        float a = 0.f;
        const float* row = &g_A[2][rowBase + t][0];
        for (int c = 0; c < CCH; c++) a += row[c] * ss[c];
        su[t] = a;
    } else if (t < 128) {
        int j = t - 64;
        float a = 0.f;
        const float* row = &g_A[1][colBase + j][0];
        for (int c = 0; c < CCH; c++) a += row[c] * ss[c];
        sw[j] = a;
    }
    float acc[4][4] = {};
    const float* A = &g_A[2][0][0];
    const float* B = &g_T1[b][0][0];
    for (int k0 = 0; k0 < CCH; k0 += 16) {
        float4 av = *(const float4*)(A + (rowBase + ar) * CCH + k0 + akseg);
        float4 bv = *(const float4*)(B + (k0 + bkk) * CCH + colBase + bcc);
        As[akseg + 0][ar] = av.x; As[akseg + 1][ar] = av.y; As[akseg + 2][ar] = av.z; As[akseg + 3][ar] = av.w;
        Bs[bkk][bcc + 0] = bv.x; Bs[bkk][bcc + 1] = bv.y; Bs[bkk][bcc + 2] = bv.z; Bs[bkk][bcc + 3] = bv.w;
        __syncthreads();
        mma16f(As, Bs, ty, tx, acc);
        __syncthreads();
    }
#pragma unroll
    for (int i = 0; i < 4; i++) {
        int ri = rowBase + ty * 4 + i;
        float u = su[ty * 4 + i], cv = g_cvec[2][ri];
#pragma unroll
        for (int j = 0; j < 4; j++) {
            int cj = colBase + tx * 4 + j;
            float ck = g_cvec[1][cj];
            g_M[b][ri][cj] = acc[i][j] + u * ck + cv * sw[tx * 4 + j] + 4096.0f * cv * ck;
        }
    }
}

// P_b = scale * M_b * Aq -> fp16; d fused (colBase==0 blocks)
__global__ void p_kernel() {
    int b = blockIdx.z;
    int rowBase = blockIdx.y * 64, colBase = blockIdx.x * 64;
    __shared__ float As[16][65], Bs[16][65];
    __shared__ float cqs[CCH];
    int t = threadIdx.x, tx = t & 15, ty = t >> 4;
    int ar = t >> 2, akseg = (t & 3) * 4;
    int bkk = t >> 4, bcc = (t & 15) * 4;
    cqs[t] = g_cvec[0][t];
    float acc[4][4] = {};
    float dacc[4] = {};
    const float* A = &g_M[b][0][0];
    const float* B = &g_A[0][0][0];
    for (int k0 = 0; k0 < CCH; k0 += 16) {
        float4 av = *(const float4*)(A + (rowBase + ar) * CCH + k0 + akseg);
        float4 bv = *(const float4*)(B + (k0 + bkk) * CCH + colBase + bcc);
        As[akseg + 0][ar] = av.x; As[akseg + 1][ar] = av.y; As[akseg + 2][ar] = av.z; As[akseg + 3][ar] = av.w;
        Bs[bkk][bcc + 0] = bv.x; Bs[bkk][bcc + 1] = bv.y; Bs[bkk][bcc + 2] = bv.z; Bs[bkk][bcc + 3] = bv.w;
        __syncthreads();
        mma16f(As, Bs, ty, tx, acc);
        if (tx == 0) {
#pragma unroll
            for (int kk = 0; kk < 16; kk++) {
                float cq = cqs[k0 + kk];
#pragma unroll
                for (int i = 0; i < 4; i++) dacc[i] += As[kk][ty * 4 + i] * cq;
            }
        }
        __syncthreads();
    }
#pragma unroll
    for (int i = 0; i < 4; i++) {
        int ri = rowBase + ty * 4 + i;
#pragma unroll
        for (int j = 0; j < 4; j++) {
            int cj = colBase + tx * 4 + j;
            g_Ph[b][ri][cj] = __float2half_rn(acc[i][j] * SCALE);
        }
        if (blockIdx.x == 0 && tx == 0) g_d[b][ri] = dacc[i] * SCALE;
    }
}

// ================= out = Ph Xh (+d), fp16 single product =================
#define OB_STRIDE 272
#define OU_AH 0
#define OU_BH 10240
#define OU_BUF (10240 + 32 * OB_STRIDE)      // 18944
#define OU_SMEM (2 * OU_BUF)                 // 37888

__global__ __launch_bounds__(256) void out_mma_kernel(float* __restrict__ out) {
    extern __shared__ char smem[];
    uint32_t sb = smem_u32(smem);
    int t = threadIdx.x, lane = t & 31, wid = t >> 5;
    int pt = blockIdx.x, mt = blockIdx.y, b = blockIdx.z;
    int wm = (wid >> 2) * 64, wn = (wid & 3) * 32;
    const __half* Ah = &g_Ph[b][mt * 128][0];
    const __half* Bh = &g_xh[b][0][pt * 128];

    float acc[4][4][4] = {};

    auto stage = [&](int buf, int kk) {
        uint32_t base = sb + buf * OU_BUF;
#pragma unroll
        for (int i = t; i < 512; i += 256) {
            int r = i >> 2, c = i & 3;
            CPA16(base + OU_AH + r * 80 + c * 16, (const char*)(Ah + (long)r * CCH + kk + c * 8));
        }
#pragma unroll
        for (int i = t; i < 512; i += 256) {
            int r = i >> 4, c = i & 15;
            CPA16(base + OU_BH + r * OB_STRIDE + c * 16, (const char*)(Bh + (long)(kk + r) * HWN + c * 8));
        }
    };

    stage(0, 0);
    CPA_COMMIT();
    const int S = 8;
    for (int s = 0; s < S; s++) {
        if (s + 1 < S) { stage((s + 1) & 1, (s + 1) * 32); CPA_COMMIT(); CPA_WAIT1(); }
        else CPA_WAIT0();
        __syncthreads();
        uint32_t base = sb + (s & 1) * OU_BUF;
#pragma unroll
        for (int ks = 0; ks < 32; ks += 16) {
            uint32_t afh[4][4], bfh[4][2];
#pragma unroll
            for (int i = 0; i < 4; i++) {
                uint32_t ao = (wm + i * 16 + (lane & 15)) * 80 + ks * 2 + (lane >> 4) * 16;
                ldsm4(afh[i], base + OU_AH + ao);
            }
#pragma unroll
            for (int j = 0; j < 2; j++) {
                uint32_t bo = (ks + (lane & 15)) * OB_STRIDE + (wn + j * 16 + (lane >> 4) * 8) * 2;
                uint32_t r[4];
                ldsm4t(r, base + OU_BH + bo);
                bfh[2 * j][0] = r[0]; bfh[2 * j][1] = r[1];
                bfh[2 * j + 1][0] = r[2]; bfh[2 * j + 1][1] = r[3];
            }
#pragma unroll
            for (int i = 0; i < 4; i++)
#pragma unroll
                for (int j = 0; j < 4; j++)
                    mma_f16(acc[i][j], afh[i], bfh[j]);
        }
        __syncthreads();
    }

#pragma unroll
    for (int i = 0; i < 4; i++) {
        int m = mt * 128 + wm + i * 16 + (lane >> 2);
        float d0 = g_d[b][m], d1 = g_d[b][m + 8];
        float* O0 = out + ((long)(b * CCH + m)) * HWN + pt * 128;
        float* O1 = O0 + 8L * HWN;
#pragma unroll
        for (int j = 0; j < 4; j++) {
            int n = wn + j * 8 + (lane & 3) * 2;
            *(float2*)(O0 + n) = make_float2(acc[i][j][0] + d0, acc[i][j][1] + d0);
            *(float2*)(O1 + n) = make_float2(acc[i][j][2] + d1, acc[i][j][3] + d1);
        }
    }
}

// ================= launch =================
extern "C" void kernel_launch(void* const* d_in, const int* in_sizes, int n_in,
                              void* d_out, int out_size) {
    const float* x = (const float*)d_in[0];

    static bool attr_done = false;
    if (!attr_done) {
        cudaFuncSetAttribute(gram_mma_kernel, cudaFuncAttributeMaxDynamicSharedMemorySize, GR_SMEM);
        cudaFuncSetAttribute(out_mma_kernel,  cudaFuncAttributeMaxDynamicSharedMemorySize, OU_SMEM);
        attr_done = true;
    }

    prep_kernel<<<dim3(CCH, BATCH), 256>>>(x);
    gram_mma_kernel<<<dim3(4, 4, BATCH), 256, GR_SMEM>>>();
    reduceG_cov_kernel<<<dim3(8, 8), 256>>>();
    wcov_kernel<<<dim3(4, 4, 3), 256>>>(
        (const float*)d_in[1], (const float*)d_in[5], (const float*)d_in[9]);
    projfin_kernel<<<96, 256>>>(
        (const float*)d_in[1], (const float*)d_in[2], (const float*)d_in[3], (const float*)d_in[4],
        (const float*)d_in[5], (const float*)d_in[6], (const float*)d_in[7], (const float*)d_in[8],
        (const float*)d_in[9], (const float*)d_in[10], (const float*)d_in[11], (const float*)d_in[12]);
    t1_kernel<<<dim3(4, 4, BATCH), 256>>>();
    m_kernel<<<dim3(4, 4, BATCH), 256>>>();
    p_kernel<<<dim3(4, 4, BATCH), 256>>>();
    out_mma_kernel<<<dim3(32, 2, BATCH), 256, OU_SMEM>>>((float*)d_out);
}

// round 16
// speedup vs baseline: 1.0488x; 1.0488x over previous
#include <cuda_runtime.h>
#include <cuda_fp16.h>
#include <cstdint>

// PatchAttentionLayer on GB300 (sm_103 baseline PTX path).
// BN folded into affine maps; attention via associativity (no NxN map).
// R16: glue chain (reduceG/cov, wcov splitK, projfin, t1, m, p) fused into ONE
// persistent 128-CTA kernel with self-resetting grid barriers (R10-proven).
// prep/gram/out stay separate at full parallelism. Launches 9 -> 4.

#define CCH 256
#define BATCH 8
#define HWN 4096
#define EPS_BN 1e-5f
#define INV_NPOS (1.0f / 32768.0f)
#define SCALE 0.125f
#define GNCTA 128

// ================= device scratch =================
__device__ __half g_xh[BATCH][CCH][HWN];   // fp16 x, [c][p]
__device__ float g_S1p[4][BATCH][CCH][CCH];
__device__ float g_s[BATCH][CCH];
__device__ float g_mean[CCH];
__device__ float g_Cov[CCH][CCH];
__device__ float g_WCp[2][3][CCH][CCH];    // split-K partials of W_tp * Cov
__device__ float g_A[3][CCH][CCH];
__device__ float g_cvec[3][CCH];
__device__ float g_G[BATCH][CCH][CCH];
__device__ float g_T1[BATCH][CCH][CCH];
__device__ float g_M[BATCH][CCH][CCH];
__device__ float g_d[BATCH][CCH];
__device__ __half g_Ph[BATCH][CCH][CCH];
// self-resetting barrier state (zero-init at load; returns to 0 each use)
__device__ unsigned g_barc[8];
__device__ unsigned g_gen[8];

// ================= helpers =================
__device__ __forceinline__ uint32_t smem_u32(const void* p) {
    uint32_t a;
    asm("{ .reg .u64 t; cvta.to.shared.u64 t, %1; cvt.u32.u64 %0, t; }" : "=r"(a) : "l"(p));
    return a;
}
__device__ __forceinline__ void ldsm4(uint32_t* r, uint32_t a) {
    asm volatile("ldmatrix.sync.aligned.m8n8.x4.shared.b16 {%0,%1,%2,%3}, [%4];"
                 : "=r"(r[0]), "=r"(r[1]), "=r"(r[2]), "=r"(r[3]) : "r"(a));
}
__device__ __forceinline__ void ldsm4t(uint32_t* r, uint32_t a) {
    asm volatile("ldmatrix.sync.aligned.m8n8.x4.trans.shared.b16 {%0,%1,%2,%3}, [%4];"
                 : "=r"(r[0]), "=r"(r[1]), "=r"(r[2]), "=r"(r[3]) : "r"(a));
}
__device__ __forceinline__ void mma_f16(float* c, const uint32_t* a, const uint32_t* b) {
    asm volatile(
        "mma.sync.aligned.m16n8k16.row.col.f32.f16.f16.f32 "
        "{%0,%1,%2,%3},{%4,%5,%6,%7},{%8,%9},{%0,%1,%2,%3};"
        : "+f"(c[0]), "+f"(c[1]), "+f"(c[2]), "+f"(c[3])
        : "r"(a[0]), "r"(a[1]), "r"(a[2]), "r"(a[3]), "r"(b[0]), "r"(b[1]));
}
#define CPA16(dst, src) asm volatile("cp.async.cg.shared.global [%0], [%1], 16;" :: "r"(dst), "l"(src))
#define CPA_COMMIT()    asm volatile("cp.async.commit_group;")
#define CPA_WAIT1()     asm volatile("cp.async.wait_group 1;")
#define CPA_WAIT0()     asm volatile("cp.async.wait_group 0;")

// self-resetting sense-reversal grid barrier (all GNCTA CTAs co-resident)
__device__ __forceinline__ void grid_bar(int k) {
    __syncthreads();
    if (threadIdx.x == 0) {
        __threadfence();
        unsigned gen = *((volatile unsigned*)&g_gen[k]);
        unsigned arrived = atomicAdd(&g_barc[k], 1u);
        if (arrived == GNCTA - 1) {
            g_barc[k] = 0;
            __threadfence();
            atomicAdd(&g_gen[k], 1u);
        } else {
            while (*((volatile unsigned*)&g_gen[k]) == gen) { __nanosleep(32); }
        }
        __threadfence();
    }
    __syncthreads();
}

// fp32 glue GEMM micro-kernel
__device__ __forceinline__ void mma16f(const float (*As)[65], const float (*Bs)[65],
                                       int ty, int tx, float acc[4][4]) {
#pragma unroll
    for (int kk = 0; kk < 16; kk++) {
        float a[4], b[4];
#pragma unroll
        for (int i = 0; i < 4; i++) a[i] = As[kk][ty * 4 + i];
#pragma unroll
        for (int j = 0; j < 4; j++) b[j] = Bs[kk][tx * 4 + j];
#pragma unroll
        for (int i = 0; i < 4; i++)
#pragma unroll
            for (int j = 0; j < 4; j++) acc[i][j] += a[i] * b[j];
    }
}

// ================= prep: fp32 -> fp16 + per-(b,c) sums =================
__global__ __launch_bounds__(256) void prep_kernel(const float* __restrict__ x) {
    int c = blockIdx.x, b = blockIdx.y;
    const float4* src = (const float4*)(x + ((long)(b * CCH + c)) * HWN);
    __half2* dh = (__half2*)&g_xh[b][c][0];
    float s = 0.f;
    for (int i = threadIdx.x; i < 1024; i += 256) {
        float4 v = src[i];
        s += (v.x + v.y) + (v.z + v.w);
        dh[2 * i]     = __halves2half2(__float2half_rn(v.x), __float2half_rn(v.y));
        dh[2 * i + 1] = __halves2half2(__float2half_rn(v.z), __float2half_rn(v.w));
    }
    __shared__ float sh[256];
    sh[threadIdx.x] = s;
    __syncthreads();
    for (int off = 128; off > 0; off >>= 1) {
        if (threadIdx.x < off) sh[threadIdx.x] += sh[threadIdx.x + off];
        __syncthreads();
    }
    if (threadIdx.x == 0) g_s[b][c] = sh[0];
}

// ================= gram: S1 = H H^T (fp16 mma, split-K x4) =================
#define GR_TILE 10240
#define GR_BUF  (2 * GR_TILE)
#define GR_SMEM (2 * GR_BUF)

__global__ __launch_bounds__(256) void gram_mma_kernel() {
    extern __shared__ char smem[];
    uint32_t sb = smem_u32(smem);
    int t = threadIdx.x, lane = t & 31, wid = t >> 5;
    int split = blockIdx.x, b = blockIdx.z;
    int mt = blockIdx.y >> 1, nt = blockIdx.y & 1;
    const __half* Ag = &g_xh[b][mt * 128][0];
    const __half* Bg = &g_xh[b][nt * 128][0];
    int k0 = split * 1024;
    int wm = (wid >> 2) * 64, wn = (wid & 3) * 32;

    float acc[4][4][4] = {};

    auto stage = [&](int buf, int kk) {
        uint32_t base = sb + buf * GR_BUF;
#pragma unroll
        for (int i = t; i < 512; i += 256) {
            int r = i >> 2, c = i & 3;
            long go = (long)r * HWN + kk + c * 8;
            uint32_t so = r * 80 + c * 16;
            CPA16(base + so,           (const char*)(Ag + go));
            CPA16(base + GR_TILE + so, (const char*)(Bg + go));
        }
    };

    stage(0, k0);
    CPA_COMMIT();
    const int S = 32;
    for (int s = 0; s < S; s++) {
        if (s + 1 < S) { stage((s + 1) & 1, k0 + (s + 1) * 32); CPA_COMMIT(); CPA_WAIT1(); }
        else CPA_WAIT0();
        __syncthreads();
        uint32_t aBase = sb + (s & 1) * GR_BUF;
        uint32_t bBase = aBase + GR_TILE;
#pragma unroll
        for (int ks = 0; ks < 32; ks += 16) {
            uint32_t af[4][4], bf[4][2];
#pragma unroll
            for (int i = 0; i < 4; i++)
                ldsm4(af[i], aBase + (wm + i * 16 + (lane & 15)) * 80 + ks * 2 + (lane >> 4) * 16);
#pragma unroll
            for (int j = 0; j < 2; j++) {
                uint32_t r[4];
                ldsm4(r, bBase + (wn + j * 16 + (lane & 15)) * 80 + ks * 2 + (lane >> 4) * 16);
                bf[2 * j][0] = r[0]; bf[2 * j][1] = r[2];
                bf[2 * j + 1][0] = r[1]; bf[2 * j + 1][1] = r[3];
            }
#pragma unroll
            for (int i = 0; i < 4; i++)
#pragma unroll
                for (int j = 0; j < 4; j++) mma_f16(acc[i][j], af[i], bf[j]);
        }
        __syncthreads();
    }

    float* dst = &g_S1p[split][b][0][0];
#pragma unroll
    for (int i = 0; i < 4; i++) {
        int m = mt * 128 + wm + i * 16 + (lane >> 2);
#pragma unroll
        for (int j = 0; j < 4; j++) {
            int n = nt * 128 + wn + j * 8 + (lane & 3) * 2;
            *(float2*)(dst + (long)m * CCH + n) = make_float2(acc[i][j][0], acc[i][j][1]);
            *(float2*)(dst + (long)(m + 8) * CCH + n) = make_float2(acc[i][j][2], acc[i][j][3]);
        }
    }
}

// ================= glue persistent kernel (128 CTAs x 256 thr) =================
// P0 reduceG+cov+mean | P1 wcov splitKx2 | P2 projfin | P3 t1 | P4 m | P5 p
__global__ __launch_bounds__(256) void glue_kernel(
    const float* __restrict__ Wq, const float* __restrict__ bq, const float* __restrict__ gq, const float* __restrict__ beq,
    const float* __restrict__ Wk, const float* __restrict__ bk, const float* __restrict__ gk, const float* __restrict__ bek,
    const float* __restrict__ Wv, const float* __restrict__ bv, const float* __restrict__ gv, const float* __restrict__ bev) {
    __shared__ float As[16][65], Bs[16][65];
    __shared__ float s1[256], s2[256];
    __shared__ float a_sh, c_sh;
    __shared__ float ss[CCH], su[64], sw[64], cqs[CCH];

    int cta = blockIdx.x, t = threadIdx.x;
    int tx = t & 15, ty = t >> 4;

    // ---- P0: reduceG + cov + mean (64 active CTAs) ----
    if (cta < 64) {
        int jt = (cta & 7) * 32, it = (cta >> 3) * 32;
        int lx = t & 31, ly = t >> 5;
        float mc = 0.f;
#pragma unroll
        for (int b = 0; b < BATCH; b++) mc += g_s[b][jt + lx];
        mc *= INV_NPOS;
        float gsum[4] = {};
        for (int b = 0; b < BATCH; b++) {
#pragma unroll
            for (int q = 0; q < 4; q++) {
                int r = ly + q * 8;
                float s = 0.f;
#pragma unroll
                for (int sp = 0; sp < 4; sp++) s += g_S1p[sp][b][it + r][jt + lx];
                g_G[b][it + r][jt + lx] = s;
                gsum[q] += s;
            }
        }
#pragma unroll
        for (int q = 0; q < 4; q++) {
            int r = ly + q * 8;
            float mr = 0.f;
#pragma unroll
            for (int b = 0; b < BATCH; b++) mr += g_s[b][it + r];
            mr *= INV_NPOS;
            g_Cov[it + r][jt + lx] = gsum[q] * INV_NPOS - mr * mc;
        }
        if (cta == 0) {
            float m = 0.f;
#pragma unroll
            for (int b = 0; b < BATCH; b++) m += g_s[b][t];
            g_mean[t] = m * INV_NPOS;
        }
    }
    grid_bar(0);

    // ---- P1: WCp[ks][tp] = W_tp[:, ksK] * Cov[ksK, :]  (96 active CTAs) ----
    if (cta < 96) {
        int tp = cta / 32, rem = cta & 31;
        int ks = rem >> 4, tile = rem & 15;
        int rowBase = (tile >> 2) * 64, colBase = (tile & 3) * 64;
        const float* A = (tp == 0) ? Wq : (tp == 1) ? Wk : Wv;
        const float* B = &g_Cov[0][0];
        int ar = t >> 2, akseg = (t & 3) * 4;
        int bkk = t >> 4, bcc = (t & 15) * 4;
        float acc[4][4] = {};
        for (int k0 = ks * 128; k0 < ks * 128 + 128; k0 += 16) {
            float4 av = *(const float4*)(A + (rowBase + ar) * CCH + k0 + akseg);
            float4 bv = *(const float4*)(B + (k0 + bkk) * CCH + colBase + bcc);
            As[akseg + 0][ar] = av.x; As[akseg + 1][ar] = av.y; As[akseg + 2][ar] = av.z; As[akseg + 3][ar] = av.w;
            Bs[bkk][bcc + 0] = bv.x; Bs[bkk][bcc + 1] = bv.y; Bs[bkk][bcc + 2] = bv.z; Bs[bkk][bcc + 3] = bv.w;
            __syncthreads();
            mma16f(As, Bs, ty, tx, acc);
            __syncthreads();
        }
#pragma unroll
        for (int i = 0; i < 4; i++)
#pragma unroll
            for (int j = 0; j < 4; j++)
                g_WCp[ks][tp][rowBase + ty * 4 + i][colBase + tx * 4 + j] = acc[i][j];
    }
    grid_bar(1);

    // ---- P2: projfin (96 active CTAs, 8 outputs each) ----
    if (cta < 96) {
        int base = cta * 8;
        int tp = base >> 8, o0 = base & 255;
        const float *W, *bb, *gg, *be;
        if (tp == 0) { W = Wq; bb = bq; gg = gq; be = beq; }
        else if (tp == 1) { W = Wk; bb = bk; gg = gk; be = bek; }
        else { W = Wv; bb = bv; gg = gv; be = bev; }
        float mt_ = g_mean[t];
#pragma unroll
        for (int r = 0; r < 8; r++) {
            int o = o0 + r;
            float w = W[o * CCH + t];
            s1[t] = (g_WCp[0][tp][o][t] + g_WCp[1][tp][o][t]) * w;
            s2[t] = w * mt_;
            __syncthreads();
            for (int off = 128; off > 0; off >>= 1) {
                if (t < off) { s1[t] += s1[t + off]; s2[t] += s2[t + off]; }
                __syncthreads();
            }
            if (t == 0) {
                float var = s1[0];
                float mu = s2[0] + bb[o];
                float a = gg[o] * rsqrtf(var + EPS_BN);
                a_sh = a;
                c_sh = (bb[o] - mu) * a + be[o];
            }
            __syncthreads();
            g_A[tp][o][t] = a_sh * w;
            if (t == 0) g_cvec[tp][o] = c_sh;
            __syncthreads();
        }
    }
    grid_bar(2);

    // ---- P3: T1 = G * Ak^T (all 128 CTAs) ----
    {
        int b = cta >> 4, rowBase = ((cta >> 2) & 3) * 64, colBase = (cta & 3) * 64;
        int r = t >> 2, kseg = (t & 3) * 4;
        float acc[4][4] = {};
        const float* A = &g_G[b][0][0];
        const float* B = &g_A[1][0][0];
        for (int k0 = 0; k0 < CCH; k0 += 16) {
            float4 av = *(const float4*)(A + (rowBase + r) * CCH + k0 + kseg);
            float4 bv = *(const float4*)(B + (colBase + r) * CCH + k0 + kseg);
            As[kseg + 0][r] = av.x; As[kseg + 1][r] = av.y; As[kseg + 2][r] = av.z; As[kseg + 3][r] = av.w;
            Bs[kseg + 0][r] = bv.x; Bs[kseg + 1][r] = bv.y; Bs[kseg + 2][r] = bv.z; Bs[kseg + 3][r] = bv.w;
            __syncthreads();
            mma16f(As, Bs, ty, tx, acc);
            __syncthreads();
        }
#pragma unroll
        for (int i = 0; i < 4; i++)
#pragma unroll
            for (int j = 0; j < 4; j++)
                g_T1[b][rowBase + ty * 4 + i][colBase + tx * 4 + j] = acc[i][j];
    }
    grid_bar(3);

    // ---- P4: M = Av*T1 + rank-1 (all 128 CTAs) ----
    {
        int b = cta >> 4, rowBase = ((cta >> 2) & 3) * 64, colBase = (cta & 3) * 64;
        int ar = t >> 2, akseg = (t & 3) * 4;
        int bkk = t >> 4, bcc = (t & 15) * 4;
        ss[t] = g_s[b][t];
        __syncthreads();
        if (t < 64) {
            float a = 0.f;
            const float* row = &g_A[2][rowBase + t][0];
            for (int c = 0; c < CCH; c++) a += row[c] * ss[c];
            su[t] = a;
        } else if (t < 128) {
            int j = t - 64;
            float a = 0.f;
            const float* row = &g_A[1][colBase + j][0];
            for (int c = 0; c < CCH; c++) a += row[c] * ss[c];
            sw[j] = a;
        }
        float acc[4][4] = {};
        const float* A = &g_A[2][0][0];
        const float* B = &g_T1[b][0][0];
        for (int k0 = 0; k0 < CCH; k0 += 16) {
            float4 av = *(const float4*)(A + (rowBase + ar) * CCH + k0 + akseg);
            float4 bv = *(const float4*)(B + (k0 + bkk) * CCH + colBase + bcc);
            As[akseg + 0][ar] = av.x; As[akseg + 1][ar] = av.y; As[akseg + 2][ar] = av.z; As[akseg + 3][ar] = av.w;
            Bs[bkk][bcc + 0] = bv.x; Bs[bkk][bcc + 1] = bv.y; Bs[bkk][bcc + 2] = bv.z; Bs[bkk][bcc + 3] = bv.w;
            __syncthreads();
            mma16f(As, Bs, ty, tx, acc);
            __syncthreads();
        }
#pragma unroll
        for (int i = 0; i < 4; i++) {
            int ri = rowBase + ty * 4 + i;
            float u = su[ty * 4 + i], cv = g_cvec[2][ri];
#pragma unroll
            for (int j = 0; j < 4; j++) {
                int cj = colBase + tx * 4 + j;
                float ck = g_cvec[1][cj];
                g_M[b][ri][cj] = acc[i][j] + u * ck + cv * sw[tx * 4 + j] + 4096.0f * cv * ck;
            }
        }
    }
    grid_bar(4);

    // ---- P5: P = SCALE*M*Aq -> fp16; d fused (all 128 CTAs) ----
    {
        int b = cta >> 4, rowBase = ((cta >> 2) & 3) * 64, colBase = (cta & 3) * 64;
        int ar = t >> 2, akseg = (t & 3) * 4;
        int bkk = t >> 4, bcc = (t & 15) * 4;
        cqs[t] = g_cvec[0][t];
        float acc[4][4] = {};
        float dacc[4] = {};
        const float* A = &g_M[b][0][0];
        const float* B = &g_A[0][0][0];
        for (int k0 = 0; k0 < CCH; k0 += 16) {
            float4 av = *(const float4*)(A + (rowBase + ar) * CCH + k0 + akseg);
            float4 bv = *(const float4*)(B + (k0 + bkk) * CCH + colBase + bcc);
            As[akseg + 0][ar] = av.x; As[akseg + 1][ar] = av.y; As[akseg + 2][ar] = av.z; As[akseg + 3][ar] = av.w;
            Bs[bkk][bcc + 0] = bv.x; Bs[bkk][bcc + 1] = bv.y; Bs[bkk][bcc + 2] = bv.z; Bs[bkk][bcc + 3] = bv.w;
            __syncthreads();
            mma16f(As, Bs, ty, tx, acc);
            if (tx == 0) {
#pragma unroll
                for (int kk = 0; kk < 16; kk++) {
                    float cq = cqs[k0 + kk];
#pragma unroll
                    for (int i = 0; i < 4; i++) dacc[i] += As[kk][ty * 4 + i] * cq;
                }
            }
            __syncthreads();
        }
#pragma unroll
        for (int i = 0; i < 4; i++) {
            int ri = rowBase + ty * 4 + i;
#pragma unroll
            for (int j = 0; j < 4; j++) {
                int cj = colBase + tx * 4 + j;
                g_Ph[b][ri][cj] = __float2half_rn(acc[i][j] * SCALE);
            }
            if ((cta & 3) == 0 && tx == 0) g_d[b][ri] = dacc[i] * SCALE;
        }
    }
}

// ================= out = Ph Xh (+d), fp16 single product =================
#define OB_STRIDE 272
#define OU_AH 0
#define OU_BH 10240
#define OU_BUF (10240 + 32 * OB_STRIDE)      // 18944
#define OU_SMEM (2 * OU_BUF)                 // 37888

__global__ __launch_bounds__(256) void out_mma_kernel(float* __restrict__ out) {
    extern __shared__ char smem[];
    uint32_t sb = smem_u32(smem);
    int t = threadIdx.x, lane = t & 31, wid = t >> 5;
    int pt = blockIdx.x, mt = blockIdx.y, b = blockIdx.z;
    int wm = (wid >> 2) * 64, wn = (wid & 3) * 32;
    const __half* Ah = &g_Ph[b][mt * 128][0];
    const __half* Bh = &g_xh[b][0][pt * 128];

    float acc[4][4][4] = {};

    auto stage = [&](int buf, int kk) {
        uint32_t base = sb + buf * OU_BUF;
#pragma unroll
        for (int i = t; i < 512; i += 256) {
            int r = i >> 2, c = i & 3;
            CPA16(base + OU_AH + r * 80 + c * 16, (const char*)(Ah + (long)r * CCH + kk + c * 8));
        }
#pragma unroll
        for (int i = t; i < 512; i += 256) {
            int r = i >> 4, c = i & 15;
            CPA16(base + OU_BH + r * OB_STRIDE + c * 16, (const char*)(Bh + (long)(kk + r) * HWN + c * 8));
        }
    };

    stage(0, 0);
    CPA_COMMIT();
    const int S = 8;
    for (int s = 0; s < S; s++) {
        if (s + 1 < S) { stage((s + 1) & 1, (s + 1) * 32); CPA_COMMIT(); CPA_WAIT1(); }
        else CPA_WAIT0();
        __syncthreads();
        uint32_t base = sb + (s & 1) * OU_BUF;
#pragma unroll
        for (int ks = 0; ks < 32; ks += 16) {
            uint32_t afh[4][4], bfh[4][2];
#pragma unroll
            for (int i = 0; i < 4; i++) {
                uint32_t ao = (wm + i * 16 + (lane & 15)) * 80 + ks * 2 + (lane >> 4) * 16;
                ldsm4(afh[i], base + OU_AH + ao);
            }
#pragma unroll
            for (int j = 0; j < 2; j++) {
                uint32_t bo = (ks + (lane & 15)) * OB_STRIDE + (wn + j * 16 + (lane >> 4) * 8) * 2;
                uint32_t r[4];
                ldsm4t(r, base + OU_BH + bo);
                bfh[2 * j][0] = r[0]; bfh[2 * j][1] = r[1];
                bfh[2 * j + 1][0] = r[2]; bfh[2 * j + 1][1] = r[3];
            }
#pragma unroll
            for (int i = 0; i < 4; i++)
#pragma unroll
                for (int j = 0; j < 4; j++)
                    mma_f16(acc[i][j], afh[i], bfh[j]);
        }
        __syncthreads();
    }

#pragma unroll
    for (int i = 0; i < 4; i++) {
        int m = mt * 128 + wm + i * 16 + (lane >> 2);
        float d0 = g_d[b][m], d1 = g_d[b][m + 8];
        float* O0 = out + ((long)(b * CCH + m)) * HWN + pt * 128;
        float* O1 = O0 + 8L * HWN;
#pragma unroll
        for (int j = 0; j < 4; j++) {
            int n = wn + j * 8 + (lane & 3) * 2;
            *(float2*)(O0 + n) = make_float2(acc[i][j][0] + d0, acc[i][j][1] + d0);
            *(float2*)(O1 + n) = make_float2(acc[i][j][2] + d1, acc[i][j][3] + d1);
        }
    }
}

// ================= launch =================
extern "C" void kernel_launch(void* const* d_in, const int* in_sizes, int n_in,
                              void* d_out, int out_size) {
    const float* x = (const float*)d_in[0];

    static bool attr_done = false;
    if (!attr_done) {
        cudaFuncSetAttribute(gram_mma_kernel, cudaFuncAttributeMaxDynamicSharedMemorySize, GR_SMEM);
        cudaFuncSetAttribute(out_mma_kernel,  cudaFuncAttributeMaxDynamicSharedMemorySize, OU_SMEM);
        attr_done = true;
    }

    prep_kernel<<<dim3(CCH, BATCH), 256>>>(x);
    gram_mma_kernel<<<dim3(4, 4, BATCH), 256, GR_SMEM>>>();
    glue_kernel<<<GNCTA, 256>>>(
        (const float*)d_in[1], (const float*)d_in[2], (const float*)d_in[3], (const float*)d_in[4],
        (const float*)d_in[5], (const float*)d_in[6], (const float*)d_in[7], (const float*)d_in[8],
        (const float*)d_in[9], (const float*)d_in[10], (const float*)d_in[11], (const float*)d_in[12]);
    out_mma_kernel<<<dim3(32, 2, BATCH), 256, OU_SMEM>>>((float*)d_out);
}

// round 17
// speedup vs baseline: 1.0620x; 1.0126x over previous
#include <cuda_runtime.h>
#include <cuda_fp16.h>
#include <cstdint>

// PatchAttentionLayer on GB300 (sm_103 baseline PTX path).
// BN folded into affine maps; attention via associativity (no NxN map).
// R17: gram fused into persistent glue kernel (128 CTAs, grid barriers);
// out rebuilt A-resident with 256-wide B tiles (64x64 warp tile, 4:1
// HMMA:ldsm). Launches 4 -> 3.

#define CCH 256
#define BATCH 8
#define HWN 4096
#define EPS_BN 1e-5f
#define INV_NPOS (1.0f / 32768.0f)
#define SCALE 0.125f
#define GNCTA 128

// ================= device scratch =================
__device__ __half g_xh[BATCH][CCH][HWN];   // fp16 x, [c][p]
__device__ float g_S1p[4][BATCH][CCH][CCH];
__device__ float g_s[BATCH][CCH];
__device__ float g_mean[CCH];
__device__ float g_Cov[CCH][CCH];
__device__ float g_WCp[2][3][CCH][CCH];
__device__ float g_A[3][CCH][CCH];
__device__ float g_cvec[3][CCH];
__device__ float g_G[BATCH][CCH][CCH];
__device__ float g_T1[BATCH][CCH][CCH];
__device__ float g_M[BATCH][CCH][CCH];
__device__ float g_d[BATCH][CCH];
__device__ __half g_Ph[BATCH][CCH][CCH];
__device__ unsigned g_barc[8];
__device__ unsigned g_gen[8];

// ================= helpers =================
__device__ __forceinline__ uint32_t smem_u32(const void* p) {
    uint32_t a;
    asm("{ .reg .u64 t; cvta.to.shared.u64 t, %1; cvt.u32.u64 %0, t; }" : "=r"(a) : "l"(p));
    return a;
}
__device__ __forceinline__ void ldsm4(uint32_t* r, uint32_t a) {
    asm volatile("ldmatrix.sync.aligned.m8n8.x4.shared.b16 {%0,%1,%2,%3}, [%4];"
                 : "=r"(r[0]), "=r"(r[1]), "=r"(r[2]), "=r"(r[3]) : "r"(a));
}
__device__ __forceinline__ void ldsm4t(uint32_t* r, uint32_t a) {
    asm volatile("ldmatrix.sync.aligned.m8n8.x4.trans.shared.b16 {%0,%1,%2,%3}, [%4];"
                 : "=r"(r[0]), "=r"(r[1]), "=r"(r[2]), "=r"(r[3]) : "r"(a));
}
__device__ __forceinline__ void mma_f16(float* c, const uint32_t* a, const uint32_t* b) {
    asm volatile(
        "mma.sync.aligned.m16n8k16.row.col.f32.f16.f16.f32 "
        "{%0,%1,%2,%3},{%4,%5,%6,%7},{%8,%9},{%0,%1,%2,%3};"
        : "+f"(c[0]), "+f"(c[1]), "+f"(c[2]), "+f"(c[3])
        : "r"(a[0]), "r"(a[1]), "r"(a[2]), "r"(a[3]), "r"(b[0]), "r"(b[1]));
}
#define CPA16(dst, src) asm volatile("cp.async.cg.shared.global [%0], [%1], 16;" :: "r"(dst), "l"(src))
#define CPA_COMMIT()    asm volatile("cp.async.commit_group;")
#define CPA_WAIT1()     asm volatile("cp.async.wait_group 1;")
#define CPA_WAIT0()     asm volatile("cp.async.wait_group 0;")

// self-resetting sense-reversal grid barrier (all GNCTA CTAs co-resident)
__device__ __forceinline__ void grid_bar(int k) {
    __syncthreads();
    if (threadIdx.x == 0) {
        __threadfence();
        unsigned gen = *((volatile unsigned*)&g_gen[k]);
        unsigned arrived = atomicAdd(&g_barc[k], 1u);
        if (arrived == GNCTA - 1) {
            g_barc[k] = 0;
            __threadfence();
            atomicAdd(&g_gen[k], 1u);
        } else {
            while (*((volatile unsigned*)&g_gen[k]) == gen) { __nanosleep(32); }
        }
        __threadfence();
    }
    __syncthreads();
}

// fp32 glue GEMM micro-kernel
__device__ __forceinline__ void mma16f(const float (*As)[65], const float (*Bs)[65],
                                       int ty, int tx, float acc[4][4]) {
#pragma unroll
    for (int kk = 0; kk < 16; kk++) {
        float a[4], b[4];
#pragma unroll
        for (int i = 0; i < 4; i++) a[i] = As[kk][ty * 4 + i];
#pragma unroll
        for (int j = 0; j < 4; j++) b[j] = Bs[kk][tx * 4 + j];
#pragma unroll
        for (int i = 0; i < 4; i++)
#pragma unroll
            for (int j = 0; j < 4; j++) acc[i][j] += a[i] * b[j];
    }
}

// ================= prep: fp32 -> fp16 + per-(b,c) sums =================
__global__ __launch_bounds__(256) void prep_kernel(const float* __restrict__ x) {
    int c = blockIdx.x, b = blockIdx.y;
    const float4* src = (const float4*)(x + ((long)(b * CCH + c)) * HWN);
    __half2* dh = (__half2*)&g_xh[b][c][0];
    float s = 0.f;
    for (int i = threadIdx.x; i < 1024; i += 256) {
        float4 v = src[i];
        s += (v.x + v.y) + (v.z + v.w);
        dh[2 * i]     = __halves2half2(__float2half_rn(v.x), __float2half_rn(v.y));
        dh[2 * i + 1] = __halves2half2(__float2half_rn(v.z), __float2half_rn(v.w));
    }
    __shared__ float sh[256];
    sh[threadIdx.x] = s;
    __syncthreads();
    for (int off = 128; off > 0; off >>= 1) {
        if (threadIdx.x < off) sh[threadIdx.x] += sh[threadIdx.x + off];
        __syncthreads();
    }
    if (threadIdx.x == 0) g_s[b][c] = sh[0];
}

// ================= glue persistent kernel (128 CTAs x 256 thr) =================
// Pg gram | P0 reduceG+cov | P1 wcov splitKx2 | P2 projfin | P3 t1 | P4 m | P5 p
#define GR_TILE 10240
#define GR_BUF  (2 * GR_TILE)
#define GR_SMEM (2 * GR_BUF)   // 40960 dynamic

__global__ __launch_bounds__(256) void glue_kernel(
    const float* __restrict__ Wq, const float* __restrict__ bq, const float* __restrict__ gq, const float* __restrict__ beq,
    const float* __restrict__ Wk, const float* __restrict__ bk, const float* __restrict__ gk, const float* __restrict__ bek,
    const float* __restrict__ Wv, const float* __restrict__ bv, const float* __restrict__ gv, const float* __restrict__ bev) {
    extern __shared__ char smem[];
    __shared__ float As[16][65], Bs[16][65];
    __shared__ float s1[256], s2[256];
    __shared__ float a_sh, c_sh;
    __shared__ float ss[CCH], su[64], sw[64], cqs[CCH];

    int cta = blockIdx.x, t = threadIdx.x;
    int tx = t & 15, ty = t >> 4;
    int lane = t & 31, wid = t >> 5;

    // ---- Pg: gram  S1p = H H^T (fp16 mma, split-K x4) ----
    {
        uint32_t sb = smem_u32(smem);
        int split = cta & 3, tileId = (cta >> 2) & 3, b = cta >> 4;
        int mt = tileId >> 1, nt = tileId & 1;
        const __half* Ag = &g_xh[b][mt * 128][0];
        const __half* Bg = &g_xh[b][nt * 128][0];
        int k0 = split * 1024;
        int wm = (wid >> 2) * 64, wn = (wid & 3) * 32;

        float acc[4][4][4] = {};

        auto stage = [&](int buf, int kk) {
            uint32_t base = sb + buf * GR_BUF;
#pragma unroll
            for (int i = t; i < 512; i += 256) {
                int r = i >> 2, c = i & 3;
                long go = (long)r * HWN + kk + c * 8;
                uint32_t so = r * 80 + c * 16;
                CPA16(base + so,           (const char*)(Ag + go));
                CPA16(base + GR_TILE + so, (const char*)(Bg + go));
            }
        };

        stage(0, k0);
        CPA_COMMIT();
        const int S = 32;
        for (int s = 0; s < S; s++) {
            if (s + 1 < S) { stage((s + 1) & 1, k0 + (s + 1) * 32); CPA_COMMIT(); CPA_WAIT1(); }
            else CPA_WAIT0();
            __syncthreads();
            uint32_t aBase = sb + (s & 1) * GR_BUF;
            uint32_t bBase = aBase + GR_TILE;
#pragma unroll
            for (int ks = 0; ks < 32; ks += 16) {
                uint32_t af[4][4], bf[4][2];
#pragma unroll
                for (int i = 0; i < 4; i++)
                    ldsm4(af[i], aBase + (wm + i * 16 + (lane & 15)) * 80 + ks * 2 + (lane >> 4) * 16);
#pragma unroll
                for (int j = 0; j < 2; j++) {
                    uint32_t r[4];
                    ldsm4(r, bBase + (wn + j * 16 + (lane & 15)) * 80 + ks * 2 + (lane >> 4) * 16);
                    bf[2 * j][0] = r[0]; bf[2 * j][1] = r[2];
                    bf[2 * j + 1][0] = r[1]; bf[2 * j + 1][1] = r[3];
                }
#pragma unroll
                for (int i = 0; i < 4; i++)
#pragma unroll
                    for (int j = 0; j < 4; j++) mma_f16(acc[i][j], af[i], bf[j]);
            }
            __syncthreads();
        }

        float* dst = &g_S1p[split][b][0][0];
#pragma unroll
        for (int i = 0; i < 4; i++) {
            int m = mt * 128 + wm + i * 16 + (lane >> 2);
#pragma unroll
            for (int j = 0; j < 4; j++) {
                int n = nt * 128 + wn + j * 8 + (lane & 3) * 2;
                *(float2*)(dst + (long)m * CCH + n) = make_float2(acc[i][j][0], acc[i][j][1]);
                *(float2*)(dst + (long)(m + 8) * CCH + n) = make_float2(acc[i][j][2], acc[i][j][3]);
            }
        }
    }
    grid_bar(0);

    // ---- P0: reduceG + cov + mean (64 active CTAs) ----
    if (cta < 64) {
        int jt = (cta & 7) * 32, it = (cta >> 3) * 32;
        int lx = t & 31, ly = t >> 5;
        float mc = 0.f;
#pragma unroll
        for (int b = 0; b < BATCH; b++) mc += g_s[b][jt + lx];
        mc *= INV_NPOS;
        float gsum[4] = {};
        for (int b = 0; b < BATCH; b++) {
#pragma unroll
            for (int q = 0; q < 4; q++) {
                int r = ly + q * 8;
                float s = 0.f;
#pragma unroll
                for (int sp = 0; sp < 4; sp++) s += g_S1p[sp][b][it + r][jt + lx];
                g_G[b][it + r][jt + lx] = s;
                gsum[q] += s;
            }
        }
#pragma unroll
        for (int q = 0; q < 4; q++) {
            int r = ly + q * 8;
            float mr = 0.f;
#pragma unroll
            for (int b = 0; b < BATCH; b++) mr += g_s[b][it + r];
            mr *= INV_NPOS;
            g_Cov[it + r][jt + lx] = gsum[q] * INV_NPOS - mr * mc;
        }
        if (cta == 0) {
            float m = 0.f;
#pragma unroll
            for (int b = 0; b < BATCH; b++) m += g_s[b][t];
            g_mean[t] = m * INV_NPOS;
        }
    }
    grid_bar(1);

    // ---- P1: WCp[ks][tp] = W_tp[:, ksK] * Cov[ksK, :]  (96 active CTAs) ----
    if (cta < 96) {
        int tp = cta / 32, rem = cta & 31;
        int ks = rem >> 4, tile = rem & 15;
        int rowBase = (tile >> 2) * 64, colBase = (tile & 3) * 64;
        const float* A = (tp == 0) ? Wq : (tp == 1) ? Wk : Wv;
        const float* B = &g_Cov[0][0];
        int ar = t >> 2, akseg = (t & 3) * 4;
        int bkk = t >> 4, bcc = (t & 15) * 4;
        float acc[4][4] = {};
        for (int k0 = ks * 128; k0 < ks * 128 + 128; k0 += 16) {
            float4 av = *(const float4*)(A + (rowBase + ar) * CCH + k0 + akseg);
            float4 bv = *(const float4*)(B + (k0 + bkk) * CCH + colBase + bcc);
            As[akseg + 0][ar] = av.x; As[akseg + 1][ar] = av.y; As[akseg + 2][ar] = av.z; As[akseg + 3][ar] = av.w;
            Bs[bkk][bcc + 0] = bv.x; Bs[bkk][bcc + 1] = bv.y; Bs[bkk][bcc + 2] = bv.z; Bs[bkk][bcc + 3] = bv.w;
            __syncthreads();
            mma16f(As, Bs, ty, tx, acc);
            __syncthreads();
        }
#pragma unroll
        for (int i = 0; i < 4; i++)
#pragma unroll
            for (int j = 0; j < 4; j++)
                g_WCp[ks][tp][rowBase + ty * 4 + i][colBase + tx * 4 + j] = acc[i][j];
    }
    grid_bar(2);

    // ---- P2: projfin (96 active CTAs, 8 outputs each) ----
    if (cta < 96) {
        int base = cta * 8;
        int tp = base >> 8, o0 = base & 255;
        const float *W, *bb, *gg, *be;
        if (tp == 0) { W = Wq; bb = bq; gg = gq; be = beq; }
        else if (tp == 1) { W = Wk; bb = bk; gg = gk; be = bek; }
        else { W = Wv; bb = bv; gg = gv; be = bev; }
        float mt_ = g_mean[t];
#pragma unroll
        for (int r = 0; r < 8; r++) {
            int o = o0 + r;
            float w = W[o * CCH + t];
            s1[t] = (g_WCp[0][tp][o][t] + g_WCp[1][tp][o][t]) * w;
            s2[t] = w * mt_;
            __syncthreads();
            for (int off = 128; off > 0; off >>= 1) {
                if (t < off) { s1[t] += s1[t + off]; s2[t] += s2[t + off]; }
                __syncthreads();
            }
            if (t == 0) {
                float var = s1[0];
                float mu = s2[0] + bb[o];
                float a = gg[o] * rsqrtf(var + EPS_BN);
                a_sh = a;
                c_sh = (bb[o] - mu) * a + be[o];
            }
            __syncthreads();
            g_A[tp][o][t] = a_sh * w;
            if (t == 0) g_cvec[tp][o] = c_sh;
            __syncthreads();
        }
    }
    grid_bar(3);

    // ---- P3: T1 = G * Ak^T (all 128 CTAs) ----
    {
        int b = cta >> 4, rowBase = ((cta >> 2) & 3) * 64, colBase = (cta & 3) * 64;
        int r = t >> 2, kseg = (t & 3) * 4;
        float acc[4][4] = {};
        const float* A = &g_G[b][0][0];
        const float* B = &g_A[1][0][0];
        for (int k0 = 0; k0 < CCH; k0 += 16) {
            float4 av = *(const float4*)(A + (rowBase + r) * CCH + k0 + kseg);
            float4 bv = *(const float4*)(B + (colBase + r) * CCH + k0 + kseg);
            As[kseg + 0][r] = av.x; As[kseg + 1][r] = av.y; As[kseg + 2][r] = av.z; As[kseg + 3][r] = av.w;
            Bs[kseg + 0][r] = bv.x; Bs[kseg + 1][r] = bv.y; Bs[kseg + 2][r] = bv.z; Bs[kseg + 3][r] = bv.w;
            __syncthreads();
            mma16f(As, Bs, ty, tx, acc);
            __syncthreads();
        }
#pragma unroll
        for (int i = 0; i < 4; i++)
#pragma unroll
            for (int j = 0; j < 4; j++)
                g_T1[b][rowBase + ty * 4 + i][colBase + tx * 4 + j] = acc[i][j];
    }
    grid_bar(4);

    // ---- P4: M = Av*T1 + rank-1 (all 128 CTAs) ----
    {
        int b = cta >> 4, rowBase = ((cta >> 2) & 3) * 64, colBase = (cta & 3) * 64;
        int ar = t >> 2, akseg = (t & 3) * 4;
        int bkk = t >> 4, bcc = (t & 15) * 4;
        ss[t] = g_s[b][t];
        __syncthreads();
        if (t < 64) {
            float a = 0.f;
            const float* row = &g_A[2][rowBase + t][0];
            for (int c = 0; c < CCH; c++) a += row[c] * ss[c];
            su[t] = a;
        } else if (t < 128) {
            int j = t - 64;
            float a = 0.f;
            const float* row = &g_A[1][colBase + j][0];
            for (int c = 0; c < CCH; c++) a += row[c] * ss[c];
            sw[j] = a;
        }
        float acc[4][4] = {};
        const float* A = &g_A[2][0][0];
        const float* B = &g_T1[b][0][0];
        for (int k0 = 0; k0 < CCH; k0 += 16) {
            float4 av = *(const float4*)(A + (rowBase + ar) * CCH + k0 + akseg);
            float4 bv = *(const float4*)(B + (k0 + bkk) * CCH + colBase + bcc);
            As[akseg + 0][ar] = av.x; As[akseg + 1][ar] = av.y; As[akseg + 2][ar] = av.z; As[akseg + 3][ar] = av.w;
            Bs[bkk][bcc + 0] = bv.x; Bs[bkk][bcc + 1] = bv.y; Bs[bkk][bcc + 2] = bv.z; Bs[bkk][bcc + 3] = bv.w;
            __syncthreads();
            mma16f(As, Bs, ty, tx, acc);
            __syncthreads();
        }
#pragma unroll
        for (int i = 0; i < 4; i++) {
            int ri = rowBase + ty * 4 + i;
            float u = su[ty * 4 + i], cv = g_cvec[2][ri];
#pragma unroll
            for (int j = 0; j < 4; j++) {
                int cj = colBase + tx * 4 + j;
                float ck = g_cvec[1][cj];
                g_M[b][ri][cj] = acc[i][j] + u * ck + cv * sw[tx * 4 + j] + 4096.0f * cv * ck;
            }
        }
    }
    grid_bar(5);

    // ---- P5: P = SCALE*M*Aq -> fp16; d fused (all 128 CTAs) ----
    {
        int b = cta >> 4, rowBase = ((cta >> 2) & 3) * 64, colBase = (cta & 3) * 64;
        int ar = t >> 2, akseg = (t & 3) * 4;
        int bkk = t >> 4, bcc = (t & 15) * 4;
        cqs[t] = g_cvec[0][t];
        float acc[4][4] = {};
        float dacc[4] = {};
        const float* A = &g_M[b][0][0];
        const float* B = &g_A[0][0][0];
        for (int k0 = 0; k0 < CCH; k0 += 16) {
            float4 av = *(const float4*)(A + (rowBase + ar) * CCH + k0 + akseg);
            float4 bv = *(const float4*)(B + (k0 + bkk) * CCH + colBase + bcc);
            As[akseg + 0][ar] = av.x; As[akseg + 1][ar] = av.y; As[akseg + 2][ar] = av.z; As[akseg + 3][ar] = av.w;
            Bs[bkk][bcc + 0] = bv.x; Bs[bkk][bcc + 1] = bv.y; Bs[bkk][bcc + 2] = bv.z; Bs[bkk][bcc + 3] = bv.w;
            __syncthreads();
            mma16f(As, Bs, ty, tx, acc);
            if (tx == 0) {
#pragma unroll
                for (int kk = 0; kk < 16; kk++) {
                    float cq = cqs[k0 + kk];
#pragma unroll
                    for (int i = 0; i < 4; i++) dacc[i] += As[kk][ty * 4 + i] * cq;
                }
            }
            __syncthreads();
        }
#pragma unroll
        for (int i = 0; i < 4; i++) {
            int ri = rowBase + ty * 4 + i;
#pragma unroll
            for (int j = 0; j < 4; j++) {
                int cj = colBase + tx * 4 + j;
                g_Ph[b][ri][cj] = __float2half_rn(acc[i][j] * SCALE);
            }
            if ((cta & 3) == 0 && tx == 0) g_d[b][ri] = dacc[i] * SCALE;
        }
    }
}

// ================= out = Ph Xh (+d): A-resident, N=256, 2 tiles/CTA =========
#define OA_STRIDE 528                    // 256 fp16 + 8 pad
#define OB2_STRIDE 528
#define OU_A 0
#define OU_A_BYTES (128 * OA_STRIDE)     // 67584
#define OU_B (OU_A_BYTES)
#define OU_B_BYTES (32 * OB2_STRIDE)     // 16896
#define OU_SMEM (OU_A_BYTES + 2 * OU_B_BYTES)  // 101376

__global__ __launch_bounds__(256, 1) void out_mma_kernel(float* __restrict__ out) {
    extern __shared__ char smem[];
    uint32_t sb = smem_u32(smem);
    int t = threadIdx.x, lane = t & 31, wid = t >> 5;
    int mt = blockIdx.y, b = blockIdx.z;
    int wm = (wid >> 2) * 64, wn = (wid & 3) * 64;
    const __half* Ah = &g_Ph[b][mt * 128][0];

    // stage resident A: 128 rows x 256 fp16
#pragma unroll
    for (int i = t; i < 4096; i += 256) {
        int r = i >> 5, c = i & 31;
        CPA16(sb + OU_A + r * OA_STRIDE + c * 16, (const char*)(Ah + (long)r * CCH + c * 8));
    }

    for (int tile = 0; tile < 2; tile++) {
        int pt = blockIdx.x + tile * 8;           // 16 tiles of 256 cols
        const __half* Bh = &g_xh[b][0][pt * 256];

        auto stageB = [&](int buf, int kk) {
            uint32_t base = sb + OU_B + buf * OU_B_BYTES;
#pragma unroll
            for (int i = t; i < 1024; i += 256) {
                int r = i >> 5, c = i & 31;
                CPA16(base + r * OB2_STRIDE + c * 16, (const char*)(Bh + (long)(kk + r) * HWN + c * 8));
            }
        };

        stageB(0, 0);
        CPA_COMMIT();

        float acc[4][8][4] = {};
        const int S = 8;  // K=256 / 32
        for (int s = 0; s < S; s++) {
            if (s + 1 < S) { stageB((s + 1) & 1, (s + 1) * 32); CPA_COMMIT(); CPA_WAIT1(); }
            else CPA_WAIT0();
            __syncthreads();
            uint32_t bBase = sb + OU_B + (s & 1) * OU_B_BYTES;
#pragma unroll
            for (int ks = 0; ks < 32; ks += 16) {
                uint32_t af[4][4], bf[8][2];
#pragma unroll
                for (int i = 0; i < 4; i++) {
                    uint32_t ao = (wm + i * 16 + (lane & 15)) * OA_STRIDE
                                + (s * 32 + ks) * 2 + (lane >> 4) * 16;
                    ldsm4(af[i], sb + OU_A + ao);
                }
#pragma unroll
                for (int j = 0; j < 4; j++) {
                    uint32_t bo = (ks + (lane & 15)) * OB2_STRIDE
                                + (wn + j * 16 + (lane >> 4) * 8) * 2;
                    uint32_t r[4];
                    ldsm4t(r, bBase + bo);
                    bf[2 * j][0] = r[0]; bf[2 * j][1] = r[1];
                    bf[2 * j + 1][0] = r[2]; bf[2 * j + 1][1] = r[3];
                }
#pragma unroll
                for (int i = 0; i < 4; i++)
#pragma unroll
                    for (int j = 0; j < 8; j++)
                        mma_f16(acc[i][j], af[i], bf[j]);
            }
            __syncthreads();
        }

#pragma unroll
        for (int i = 0; i < 4; i++) {
            int m = mt * 128 + wm + i * 16 + (lane >> 2);
            float d0 = g_d[b][m], d1 = g_d[b][m + 8];
            float* O0 = out + ((long)(b * CCH + m)) * HWN + pt * 256;
            float* O1 = O0 + 8L * HWN;
#pragma unroll
            for (int j = 0; j < 8; j++) {
                int n = wn + j * 8 + (lane & 3) * 2;
                *(float2*)(O0 + n) = make_float2(acc[i][j][0] + d0, acc[i][j][1] + d0);
                *(float2*)(O1 + n) = make_float2(acc[i][j][2] + d1, acc[i][j][3] + d1);
            }
        }
        __syncthreads();  // B buffers reused by next tile
    }
}

// ================= launch =================
extern "C" void kernel_launch(void* const* d_in, const int* in_sizes, int n_in,
                              void* d_out, int out_size) {
    const float* x = (const float*)d_in[0];

    static bool attr_done = false;
    if (!attr_done) {
        cudaFuncSetAttribute(glue_kernel,    cudaFuncAttributeMaxDynamicSharedMemorySize, GR_SMEM);
        cudaFuncSetAttribute(out_mma_kernel, cudaFuncAttributeMaxDynamicSharedMemorySize, OU_SMEM);
        attr_done = true;
    }

    prep_kernel<<<dim3(CCH, BATCH), 256>>>(x);
    glue_kernel<<<GNCTA, 256, GR_SMEM>>>(
        (const float*)d_in[1], (const float*)d_in[2], (const float*)d_in[3], (const float*)d_in[4],
        (const float*)d_in[5], (const float*)d_in[6], (const float*)d_in[7], (const float*)d_in[8],
        (const float*)d_in[9], (const float*)d_in[10], (const float*)d_in[11], (const float*)d_in[12]);
    out_mma_kernel<<<dim3(8, 2, BATCH), 256, OU_SMEM>>>((float*)d_out);
}